// round 17
// baseline (speedup 1.0000x reference)
#include <cuda_runtime.h>
#include <cuda_fp16.h>
#include <cstdint>

// GeodesicLayer, three-kernel split (fused persistent gather+GEMM):
//  K0: W -> fp16 padded Bt[n][k] in gmem; resets tile counter.
//  K2: persistent CTAs, 640 threads: warps 0-15 MMA (one t each), warps 16-19
//      producer warps gathering h for chunk c+3 straight into the SMEM A-stage
//      (transposed 8-lanes/row float2 gather -> half2 STS in ldmatrix layout).
//      4-stage ring, one __syncthreads per chunk slot. Dynamic MTILE=32 queue.
//      Per-warp t-slab STG to g_part.
//  K3: out[n,o] = max_t g_part[t][n][o]

#define NVERT 30000
#define NVPAD 30016
#define KTOT  1280

#define BT_STRIDE_EL 1288

__device__ __half g_bt[32 * BT_STRIDE_EL];
__device__ float g_part[(size_t)16 * NVPAD * 32];       // [t][n][o]
__device__ int g_ctr;

typedef unsigned int u32;

__device__ __forceinline__ u32 s2u(const void* p) {
    u32 a;
    asm("{ .reg .u64 t; cvta.to.shared.u64 t, %1; cvt.u32.u64 %0, t; }"
        : "=r"(a) : "l"(p));
    return a;
}

// ====================== kernel 0: prep B + counter reset ======================
__global__ __launch_bounds__(512)
void geo_prep_b(const float* __restrict__ wts)
{
    if (blockIdx.x == 0 && threadIdx.x == 0) g_ctr = 0;
    const int i0 = blockIdx.x * 1024 + threadIdx.x;
    #pragma unroll
    for (int rep = 0; rep < 2; ++rep) {
        int idx = i0 + rep * 512;             // 0..40959
        float w = wts[idx];
        int k = idx >> 5, n = idx & 31;
        g_bt[n * BT_STRIDE_EL + k] = __float2half_rn(w);
    }
}

// ====================== kernel 2: fused persistent gather + GEMM ==============
#define MTILE    32
#define NTILES   (NVPAD / MTILE)               // 938
#define NTHREADS 640                           // 16 MMA warps + 4 producer warps
#define GRID_K2  152

#define CHUNKS   5                             // K-chunks of 256 per tile
#define CHUNK_K  256
#define BT_BYTES     (32 * BT_STRIDE_EL * 2)   // 82432
#define OFF_A        BT_BYTES                  // 82432 (16B aligned)
#define A_ROW_B      528                       // 256 fp16 = 512 B + 16 pad
#define A_STAGE      (MTILE * A_ROW_B)         // 16896
#define NSTAGES      4
#define OFF_NEXT     (OFF_A + NSTAGES * A_STAGE)   // 150016
#define SMEM_TOTAL   (OFF_NEXT + 16)               // 150032

__device__ __forceinline__ void ldsm4(u32& r0, u32& r1, u32& r2, u32& r3, u32 addr) {
    asm volatile("ldmatrix.sync.aligned.m8n8.x4.shared.b16 {%0,%1,%2,%3}, [%4];"
        : "=r"(r0), "=r"(r1), "=r"(r2), "=r"(r3) : "r"(addr));
}
__device__ __forceinline__ void mma_f16(float* d, const u32* a, u32 b0, u32 b1) {
    asm volatile(
        "mma.sync.aligned.m16n8k16.row.col.f32.f16.f16.f32 "
        "{%0,%1,%2,%3}, {%4,%5,%6,%7}, {%8,%9}, {%0,%1,%2,%3};"
        : "+f"(d[0]), "+f"(d[1]), "+f"(d[2]), "+f"(d[3])
        : "r"(a[0]), "r"(a[1]), "r"(a[2]), "r"(a[3]), "r"(b0), "r"(b1));
}
__device__ __forceinline__ void cp16(u32 dst, const void* src) {
    asm volatile("cp.async.cg.shared.global [%0], [%1], 16;"
                 :: "r"(dst), "l"(src) : "memory");
}

// Producer warps (128 threads): gather chunk pc (bins 16*pc..16*pc+15) of tile
// pt straight into stage s. 8 lanes per conn row (lane c2 owns channels
// 2*c2, 2*c2+1), 16 rows concurrent, 32 iterations.
__device__ __forceinline__ void gather_chunk(
    int pt, int pc, int s, u32 sb, int gtid,
    const float* __restrict__ x,
    const int*   __restrict__ cidx,
    const float* __restrict__ cval)
{
    const int c2 = gtid & 7;
    const int rs = gtid >> 3;            // 0..15
    const u32 stb = sb + OFF_A + (u32)s * A_STAGE + (u32)(c2 * 4);
    const float2* xp = (const float2*)x;
    #pragma unroll 4
    for (int it = 0; it < 32; ++it) {
        int r  = it * 16 + rs;           // 0..511
        int v  = r >> 4, bl = r & 15;
        int vg = pt * MTILE + v;
        float h0 = 0.f, h1 = 0.f;
        if (vg < NVERT) {
            size_t grow = ((size_t)vg * 80 + pc * 16 + bl) * 3;
            int   i0 = __ldg(cidx + grow), i1 = __ldg(cidx + grow + 1),
                  i2 = __ldg(cidx + grow + 2);
            float v0 = __ldg(cval + grow), v1 = __ldg(cval + grow + 1),
                  v2 = __ldg(cval + grow + 2);
            float2 a = __ldg(xp + i0 * 8 + c2);
            float2 b = __ldg(xp + i1 * 8 + c2);
            float2 c = __ldg(xp + i2 * 8 + c2);
            h0 = v0 * a.x + v1 * b.x + v2 * c.x;
            h1 = v0 * a.y + v1 * b.y + v2 * c.y;
        }
        __half2 hh = __floats2half2_rn(h0, h1);
        u32 addr = stb + (u32)(v * A_ROW_B + bl * 32);
        asm volatile("st.shared.b32 [%0], %1;" :: "r"(addr), "r"(*(u32*)&hh));
    }
}

__global__ __launch_bounds__(NTHREADS, 1)
void geo_mma_kernel(const float* __restrict__ x,
                    const int*   __restrict__ cidx,
                    const float* __restrict__ cval)
{
    extern __shared__ char smem[];
    const u32 sb   = s2u(smem);
    const int tid  = threadIdx.x;
    const int warp = tid >> 5;             // 0-15: MMA (== t value), 16-19: producer
    const int lane = tid & 31;

    // ---- load B once via cp.async (all threads participate) ----
    {
        const char* src = (const char*)g_bt;
        for (int q = tid; q < BT_BYTES / 16; q += NTHREADS)
            cp16(sb + q * 16, src + q * 16);
        asm volatile("cp.async.commit_group;" ::: "memory");
    }

    // ldmatrix lane addressing (validated round 8)
    const u32 a_lane = (u32)(((lane & 7) + ((lane >> 3) & 1) * 8) * A_ROW_B
                             + ((lane >> 4) & 1) * 16);
    const u32 b_row  = (u32)((lane & 7) + ((lane >> 4) & 1) * 8);
    const u32 b_lane = b_row * (BT_STRIDE_EL * 2) + (u32)(((lane >> 3) & 1) * 16);
    const u32 bbase  = sb;
    int* s_next = (int*)(smem + OFF_NEXT);

    if (tid == 0) *s_next = atomicAdd(&g_ctr, 1);
    __syncthreads();
    int tile = *s_next;

    // ---- prologue: producer warps fill stages 0,1,2 of first tile ----
    if (warp >= 16 && tile < NTILES) {
        const int gtid = tid - 512;
        gather_chunk(tile, 0, 0, sb, gtid, x, cidx, cval);
        gather_chunk(tile, 1, 1, sb, gtid, x, cidx, cval);
        gather_chunk(tile, 2, 2, sb, gtid, x, cidx, cval);
    }
    asm volatile("cp.async.wait_group 0;" ::: "memory");   // B resident
    __syncthreads();                                       // stages 0-2 + B ready

    int ist = 3;    // stage the producers fill next
    int cst = 0;    // stage the MMA warps consume next

    while (tile < NTILES) {
        const int vbase = tile * MTILE;

        float acc[2][4][4];
        #pragma unroll
        for (int m = 0; m < 2; ++m)
            #pragma unroll
            for (int n = 0; n < 4; ++n)
                #pragma unroll
                for (int q = 0; q < 4; ++q) acc[m][n][q] = 0.f;

        for (int c = 0; c < CHUNKS; ++c) {
            if (c == 0 && tid == 0) *s_next = atomicAdd(&g_ctr, 1);

            if (warp < 16) {
                // ---- consumer: MMA on chunk c (stage cst) ----
                const u32 abase = sb + OFF_A + (u32)cst * A_STAGE;
                int wbin = (16 * c + 5 * warp) % 80;
                #pragma unroll
                for (int j = 0; j < 16; ++j) {
                    const u32 boff = b_lane + (u32)wbin * 32;
                    u32 bh[2][4];
                    ldsm4(bh[0][0], bh[0][1], bh[0][2], bh[0][3], bbase + boff);
                    ldsm4(bh[1][0], bh[1][1], bh[1][2], bh[1][3],
                          bbase + boff + 16 * BT_STRIDE_EL * 2);
                    #pragma unroll
                    for (int mt = 0; mt < 2; ++mt) {
                        const u32 aaddr = abase
                            + (u32)(mt * 16 * A_ROW_B + j * 32) + a_lane;
                        u32 ah[4];
                        ldsm4(ah[0], ah[1], ah[2], ah[3], aaddr);
                        #pragma unroll
                        for (int nt = 0; nt < 4; ++nt)
                            mma_f16(acc[mt][nt], ah,
                                    bh[nt >> 1][(nt & 1) * 2],
                                    bh[nt >> 1][(nt & 1) * 2 + 1]);
                    }
                    ++wbin; if (wbin == 80) wbin = 0;
                }
            } else {
                // ---- producer: gather chunk c+3 (maybe next tile) into ist ----
                // s_next is read only for c>=2; written at c==0 and ordered by
                // the end-of-slot syncthreads of slots 0 and 1.
                int pt = tile, pc = c + 3;
                if (pc >= CHUNKS) { pt = *s_next; pc -= CHUNKS; }
                if (pt < NTILES)
                    gather_chunk(pt, pc, ist, sb, tid - 512, x, cidx, cval);
            }
            cst = (cst + 1) & 3;
            ist = (ist + 1) & 3;
            __syncthreads();   // slot handoff: stage fills visible, consumption done
        }

        // ---- epilogue: MMA warps STG their t-slab (no barrier needed) ----
        if (warp < 16) {
            float* basep = g_part + ((size_t)warp * NVPAD + vbase) * 32;
            #pragma unroll
            for (int mt = 0; mt < 2; ++mt)
                #pragma unroll
                for (int nt = 0; nt < 4; ++nt) {
                    int v = mt * 16 + (lane >> 2);
                    int o = nt * 8 + (lane & 3) * 2;
                    *(float2*)(basep + v * 32 + o) =
                        make_float2(acc[mt][nt][0], acc[mt][nt][1]);
                    *(float2*)(basep + (v + 8) * 32 + o) =
                        make_float2(acc[mt][nt][2], acc[mt][nt][3]);
                }
        }
        tile = *s_next;   // written at c==0, ordered by the 5 slot syncs
    }
}

// ====================== kernel 3: max over t ======================
__global__ __launch_bounds__(256)
void geo_max_kernel(float* __restrict__ out)
{
    const int idx = blockIdx.x * 256 + threadIdx.x;     // float4 index
    if (idx >= NVERT * 8) return;
    const float4* p = (const float4*)g_part;
    float4 m = p[idx];
    #pragma unroll
    for (int t = 1; t < 16; ++t) {
        float4 v = p[(size_t)t * NVPAD * 8 + idx];
        m.x = fmaxf(m.x, v.x);
        m.y = fmaxf(m.y, v.y);
        m.z = fmaxf(m.z, v.z);
        m.w = fmaxf(m.w, v.w);
    }
    ((float4*)out)[idx] = m;
}

extern "C" void kernel_launch(void* const* d_in, const int* in_sizes, int n_in,
                              void* d_out, int out_size)
{
    const float* x    = (const float*)d_in[0];
    const int*   cidx = (const int*)  d_in[1];
    const float* cval = (const float*)d_in[2];
    const float* wts  = (const float*)d_in[3];
    float* out = (float*)d_out;

    geo_prep_b<<<40, 512>>>(wts);

    cudaFuncSetAttribute(geo_mma_kernel,
                         cudaFuncAttributeMaxDynamicSharedMemorySize, SMEM_TOTAL);
    geo_mma_kernel<<<GRID_K2, NTHREADS, SMEM_TOTAL>>>(x, cidx, cval);

    geo_max_kernel<<<(NVERT * 8 + 255) / 256, 256>>>(out);
}